// round 4
// baseline (speedup 1.0000x reference)
#include <cuda_runtime.h>
#include <math.h>

#define TT   2048
#define HID  2048
#define NH   16
#define DH   128

// ---------------- scratch (static device memory; no allocations) -------------
__device__ float g_q[TT * HID];
__device__ float g_k[TT * HID];
__device__ float g_v[TT * HID];
__device__ float g_attn[TT * HID];
__device__ float g_gate[TT * NH];

// ============================================================================
// GEMM: C[2048 x 2048] = A[2048 x 2048] @ B[2048 x N], ldb = row stride of B.
// 128x128 tile, BK=16, 256 threads, 8x8 per thread, register-staged
// double buffering of the global loads.
// ============================================================================
__global__ __launch_bounds__(256, 2)
void gemm_f32(const float* __restrict__ A, const float* __restrict__ B,
              float* __restrict__ C, int ldb)
{
    __shared__ float As[16][132];   // [k][m], padded
    __shared__ float Bs[16][128];   // [k][n]

    const int tid  = threadIdx.x;
    const int bm   = blockIdx.y * 128;
    const int bn   = blockIdx.x * 128;
    const int tm   = (tid >> 4) * 8;
    const int tn   = (tid & 15) * 8;
    const int arow = tid >> 2;            // 0..63
    const int acol = (tid & 3) * 4;       // 0,4,8,12
    const int brow = tid >> 5;            // 0..7
    const int bcol = (tid & 31) * 4;      // 0..124

    float acc[8][8];
#pragma unroll
    for (int i = 0; i < 8; i++)
#pragma unroll
        for (int j = 0; j < 8; j++) acc[i][j] = 0.f;

    // prologue loads (k0 = 0)
    float4 ra0 = *(const float4*)(A + (size_t)(bm + arow)      * 2048 + acol);
    float4 ra1 = *(const float4*)(A + (size_t)(bm + arow + 64) * 2048 + acol);
    float4 rb0 = *(const float4*)(B + (size_t)(brow)     * ldb + bn + bcol);
    float4 rb1 = *(const float4*)(B + (size_t)(brow + 8) * ldb + bn + bcol);

    int k0 = 0;
    while (true) {
        // commit staged tile to smem
        As[acol + 0][arow] = ra0.x; As[acol + 1][arow] = ra0.y;
        As[acol + 2][arow] = ra0.z; As[acol + 3][arow] = ra0.w;
        As[acol + 0][arow + 64] = ra1.x; As[acol + 1][arow + 64] = ra1.y;
        As[acol + 2][arow + 64] = ra1.z; As[acol + 3][arow + 64] = ra1.w;
        *(float4*)&Bs[brow][bcol]     = rb0;
        *(float4*)&Bs[brow + 8][bcol] = rb1;
        __syncthreads();

        const int k1 = k0 + 16;
        if (k1 < 2048) {   // issue next tile loads (overlap with compute)
            ra0 = *(const float4*)(A + (size_t)(bm + arow)      * 2048 + k1 + acol);
            ra1 = *(const float4*)(A + (size_t)(bm + arow + 64) * 2048 + k1 + acol);
            rb0 = *(const float4*)(B + (size_t)(k1 + brow)     * ldb + bn + bcol);
            rb1 = *(const float4*)(B + (size_t)(k1 + brow + 8) * ldb + bn + bcol);
        }

#pragma unroll
        for (int k = 0; k < 16; k++) {
            float ra[8], rb[8];
            *(float4*)(ra)     = *(const float4*)&As[k][tm];
            *(float4*)(ra + 4) = *(const float4*)&As[k][tm + 4];
            *(float4*)(rb)     = *(const float4*)&Bs[k][tn];
            *(float4*)(rb + 4) = *(const float4*)&Bs[k][tn + 4];
#pragma unroll
            for (int i = 0; i < 8; i++)
#pragma unroll
                for (int j = 0; j < 8; j++)
                    acc[i][j] += ra[i] * rb[j];
        }

        k0 = k1;
        if (k0 >= 2048) break;
        __syncthreads();
    }

#pragma unroll
    for (int i = 0; i < 8; i++) {
        float4 o0 = make_float4(acc[i][0], acc[i][1], acc[i][2], acc[i][3]);
        float4 o1 = make_float4(acc[i][4], acc[i][5], acc[i][6], acc[i][7]);
        *(float4*)(C + (size_t)(bm + tm + i) * 2048 + bn + tn)     = o0;
        *(float4*)(C + (size_t)(bm + tm + i) * 2048 + bn + tn + 4) = o1;
    }
}

// ============================================================================
// gate logits: gate[T][16] = hidden @ Wq[:, 2048:2064]  (fp32, exact sign)
// ============================================================================
__global__ __launch_bounds__(256)
void gate_kernel(const float* __restrict__ A, const float* __restrict__ Wq,
                 float* __restrict__ gate)
{
    __shared__ float As[32][65];   // [k][tok]
    __shared__ float Ws[32][16];   // [k][g]
    const int t0  = blockIdx.x * 64;
    const int tid = threadIdx.x;
    const int tok = tid >> 2;        // 0..63
    const int g0  = (tid & 3) * 4;   // 0,4,8,12

    float acc[4] = {0.f, 0.f, 0.f, 0.f};

    for (int k0 = 0; k0 < 2048; k0 += 32) {
#pragma unroll
        for (int i = 0; i < 2; i++) {
            int idx = tid + 256 * i;           // 0..511
            int r = idx >> 3, c4 = (idx & 7) * 4;
            float4 a = *(const float4*)(A + (size_t)(t0 + r) * 2048 + k0 + c4);
            As[c4 + 0][r] = a.x; As[c4 + 1][r] = a.y;
            As[c4 + 2][r] = a.z; As[c4 + 3][r] = a.w;
        }
#pragma unroll
        for (int i = 0; i < 2; i++) {
            int j = tid + 256 * i;             // 0..511
            int r = j >> 4, c = j & 15;
            Ws[r][c] = Wq[(size_t)(k0 + r) * 2064 + 2048 + c];
        }
        __syncthreads();
#pragma unroll
        for (int k = 0; k < 32; k++) {
            float a = As[k][tok];
            acc[0] += a * Ws[k][g0 + 0];
            acc[1] += a * Ws[k][g0 + 1];
            acc[2] += a * Ws[k][g0 + 2];
            acc[3] += a * Ws[k][g0 + 3];
        }
        __syncthreads();
    }
#pragma unroll
    for (int j = 0; j < 4; j++)
        gate[(size_t)(t0 + tok) * 16 + g0 + j] = acc[j];
}

// ============================================================================
// RMSNorm (over full 2048) + RoPE (per head, D=128), in place.
// grid (T, 2): y==0 -> q with q_norm_w, y==1 -> k with k_norm_w.
// ============================================================================
__global__ __launch_bounds__(256)
void norm_rope(float* __restrict__ xq, float* __restrict__ xk,
               const float* __restrict__ qw, const float* __restrict__ kw,
               const int* __restrict__ pos)
{
    const int t = blockIdx.x;
    float* row      = (blockIdx.y == 0 ? xq : xk) + (size_t)t * 2048;
    const float* w  = (blockIdx.y == 0 ? qw : kw);

    __shared__ float sm[2048];
    __shared__ float red[8];

    float ss = 0.f;
    for (int i = threadIdx.x; i < 2048; i += 256) {
        float v = row[i]; sm[i] = v; ss += v * v;
    }
#pragma unroll
    for (int o = 16; o; o >>= 1) ss += __shfl_xor_sync(0xffffffffu, ss, o);
    if ((threadIdx.x & 31) == 0) red[threadIdx.x >> 5] = ss;
    __syncthreads();

    float tot = 0.f;
#pragma unroll
    for (int i = 0; i < 8; i++) tot += red[i];
    const float rinv = rsqrtf(tot * (1.0f / 2048.0f) + 1e-6f);
    const float p = (float)pos[t];

    for (int pr = threadIdx.x; pr < 1024; pr += 256) {
        int hh = pr >> 6, i = pr & 63;
        float invf = powf(500000.0f, -(float)(2 * i) * (1.0f / 128.0f));
        float ang = p * invf;
        float sn, cs; sincosf(ang, &sn, &cs);
        int i1 = hh * 128 + i, i2 = i1 + 64;
        float x1 = sm[i1] * rinv * w[i1];
        float x2 = sm[i2] * rinv * w[i2];
        row[i1] = x1 * cs - x2 * sn;
        row[i2] = x2 * cs + x1 * sn;
    }
}

// ============================================================================
// Fused gated attention: per query row the mask is either causal (gate>0)
// or causal ∧ (t - j < 128). Flash-2 streaming softmax, fp32.
// grid (T/64, H), 256 threads, ~114 KB dynamic smem (1 CTA/SM).
// ============================================================================
#define ATT_SMEM ((128*64*2 + 64*128 + 64*68 + 4*64) * 4)

__device__ __forceinline__ void fma8(float* o, float p, float4 va, float4 vb)
{
    o[0] += p * va.x; o[1] += p * va.y; o[2] += p * va.z; o[3] += p * va.w;
    o[4] += p * vb.x; o[5] += p * vb.y; o[6] += p * vb.z; o[7] += p * vb.w;
}

__global__ __launch_bounds__(256)
void attn_kernel(const float* __restrict__ gq, const float* __restrict__ gk,
                 const float* __restrict__ gv, const float* __restrict__ gate,
                 float* __restrict__ outp)
{
    extern __shared__ float smx[];
    float* Qs = smx;                 // [128][64]  d-major
    float* Ks = Qs + 128 * 64;       // [128][64]  d-major
    float* Vs = Ks + 128 * 64;       // [64][128]  k-major
    float* Ss = Vs + 64 * 128;       // [64][68]
    float* aS = Ss + 64 * 68;        // alpha[64]
    float* mS = aS + 64;
    float* lS = mS + 64;
    float* gS = lS + 64;

    const int tid = threadIdx.x;
    const int qt = blockIdx.x, h = blockIdx.y;
    const int t0 = qt * 64;
    const float scale = 0.08838834764831843f;   // 128^-0.5

    for (int idx = tid; idx < 64 * 128; idx += 256) {
        int r = idx >> 7, d = idx & 127;
        Qs[d * 64 + r] = gq[(size_t)(t0 + r) * 2048 + h * 128 + d];
    }
    if (tid < 64) {
        mS[tid] = -1e30f; lS[tid] = 0.f;
        gS[tid] = (gate[(size_t)(t0 + tid) * 16 + h] > 0.f) ? 1.f : 0.f;
    }

    const int tq   = tid & 15, tk  = tid >> 4;   // phase A (score)
    const int td   = tid & 15, tq2 = tid >> 4;   // phase B (PV)
    const int srow = tid >> 2, spart = tid & 3;  // softmax

    float O[4][8];
#pragma unroll
    for (int i = 0; i < 4; i++)
#pragma unroll
        for (int j = 0; j < 8; j++) O[i][j] = 0.f;

    for (int kt = 0; kt <= qt; kt++) {
        const int k0 = kt * 64;
        __syncthreads();   // K/V/S buffers free; Q + init visible on first iter
        for (int idx = tid; idx < 64 * 128; idx += 256) {
            int r = idx >> 7, d = idx & 127;
            Ks[d * 64 + r] = gk[(size_t)(k0 + r) * 2048 + h * 128 + d];
            Vs[idx]        = gv[(size_t)(k0 + r) * 2048 + h * 128 + d];
        }
        __syncthreads();

        // ---- phase A: S = Q K^T (4x4 per thread) ----
        float s[4][4];
#pragma unroll
        for (int i = 0; i < 4; i++)
#pragma unroll
            for (int j = 0; j < 4; j++) s[i][j] = 0.f;

        const float* Qb = Qs + tq * 4;
        const float* Kb = Ks + tk * 4;
#pragma unroll 4
        for (int d = 0; d < 128; d++) {
            const float4 a = *(const float4*)(Qb + d * 64);
            const float4 b = *(const float4*)(Kb + d * 64);
            s[0][0] += a.x*b.x; s[0][1] += a.x*b.y; s[0][2] += a.x*b.z; s[0][3] += a.x*b.w;
            s[1][0] += a.y*b.x; s[1][1] += a.y*b.y; s[1][2] += a.y*b.z; s[1][3] += a.y*b.w;
            s[2][0] += a.z*b.x; s[2][1] += a.z*b.y; s[2][2] += a.z*b.z; s[2][3] += a.z*b.w;
            s[3][0] += a.w*b.x; s[3][1] += a.w*b.y; s[3][2] += a.w*b.z; s[3][3] += a.w*b.w;
        }

        const int jb = k0 + tk * 4;
#pragma unroll
        for (int i = 0; i < 4; i++) {
            const int q  = tq * 4 + i;
            const int tg = t0 + q;
            const bool glob = gS[q] > 0.5f;
            const int lo = glob ? -0x7fffffff : (tg - 127);   // min allowed key idx
            float4 o;
            o.x = (jb + 0 <= tg && jb + 0 >= lo) ? s[i][0] * scale : -1e30f;
            o.y = (jb + 1 <= tg && jb + 1 >= lo) ? s[i][1] * scale : -1e30f;
            o.z = (jb + 2 <= tg && jb + 2 >= lo) ? s[i][2] * scale : -1e30f;
            o.w = (jb + 3 <= tg && jb + 3 >= lo) ? s[i][3] * scale : -1e30f;
            *(float4*)(Ss + q * 68 + tk * 4) = o;
        }
        __syncthreads();

        // ---- streaming softmax update (4 threads per row) ----
        {
            float* rowp = Ss + srow * 68 + spart * 16;
            float mloc = -1e30f;
#pragma unroll
            for (int c = 0; c < 16; c++) mloc = fmaxf(mloc, rowp[c]);
            mloc = fmaxf(mloc, __shfl_xor_sync(0xffffffffu, mloc, 1));
            mloc = fmaxf(mloc, __shfl_xor_sync(0xffffffffu, mloc, 2));
            const float mold = mS[srow];
            const float mnew = fmaxf(mold, mloc);
            float lsum = 0.f;
#pragma unroll
            for (int c = 0; c < 16; c++) {
                float v = rowp[c];
                float pp = (v > -1e29f) ? expf(v - mnew) : 0.f;
                rowp[c] = pp; lsum += pp;
            }
            lsum += __shfl_xor_sync(0xffffffffu, lsum, 1);
            lsum += __shfl_xor_sync(0xffffffffu, lsum, 2);
            if (spart == 0) {
                float alpha = expf(mold - mnew);    // underflows to 0 cleanly
                lS[srow] = lS[srow] * alpha + lsum;
                mS[srow] = mnew;
                aS[srow] = alpha;
            }
        }
        __syncthreads();

        // ---- phase B: O = O*alpha + P @ V (4q x 8d per thread) ----
        {
            const int q0 = tq2 * 4, d0 = td * 8;
            const float al0 = aS[q0], al1 = aS[q0+1], al2 = aS[q0+2], al3 = aS[q0+3];
#pragma unroll
            for (int j = 0; j < 8; j++) {
                O[0][j] *= al0; O[1][j] *= al1; O[2][j] *= al2; O[3][j] *= al3;
            }
            for (int kk = 0; kk < 64; kk += 4) {
                float4 p0 = *(const float4*)(Ss + (q0+0) * 68 + kk);
                float4 p1 = *(const float4*)(Ss + (q0+1) * 68 + kk);
                float4 p2 = *(const float4*)(Ss + (q0+2) * 68 + kk);
                float4 p3 = *(const float4*)(Ss + (q0+3) * 68 + kk);
                const float* vb = Vs + kk * 128 + d0;
                float4 va0, va1;
                va0 = *(const float4*)(vb);            va1 = *(const float4*)(vb + 4);
                fma8(O[0], p0.x, va0, va1); fma8(O[1], p1.x, va0, va1);
                fma8(O[2], p2.x, va0, va1); fma8(O[3], p3.x, va0, va1);
                va0 = *(const float4*)(vb + 128);      va1 = *(const float4*)(vb + 132);
                fma8(O[0], p0.y, va0, va1); fma8(O[1], p1.y, va0, va1);
                fma8(O[2], p2.y, va0, va1); fma8(O[3], p3.y, va0, va1);
                va0 = *(const float4*)(vb + 256);      va1 = *(const float4*)(vb + 260);
                fma8(O[0], p0.z, va0, va1); fma8(O[1], p1.z, va0, va1);
                fma8(O[2], p2.z, va0, va1); fma8(O[3], p3.z, va0, va1);
                va0 = *(const float4*)(vb + 384);      va1 = *(const float4*)(vb + 388);
                fma8(O[0], p0.w, va0, va1); fma8(O[1], p1.w, va0, va1);
                fma8(O[2], p2.w, va0, va1); fma8(O[3], p3.w, va0, va1);
            }
        }
    }

    // ---- epilogue: normalize and store blended output ----
    {
        const int q0 = tq2 * 4, d0 = td * 8;
#pragma unroll
        for (int i = 0; i < 4; i++) {
            const float linv = 1.0f / lS[q0 + i];
            const int t = t0 + q0 + i;
            float4 o0 = make_float4(O[i][0]*linv, O[i][1]*linv, O[i][2]*linv, O[i][3]*linv);
            float4 o1 = make_float4(O[i][4]*linv, O[i][5]*linv, O[i][6]*linv, O[i][7]*linv);
            *(float4*)(outp + (size_t)t * 2048 + h * 128 + d0)     = o0;
            *(float4*)(outp + (size_t)t * 2048 + h * 128 + d0 + 4) = o1;
        }
    }
}

// ============================================================================
extern "C" void kernel_launch(void* const* d_in, const int* in_sizes, int n_in,
                              void* d_out, int out_size)
{
    const float* hidden = (const float*)d_in[0];
    const int*   pos    = (const int*)  d_in[1];
    const float* Wq     = (const float*)d_in[2];
    const float* Wk     = (const float*)d_in[3];
    const float* Wv     = (const float*)d_in[4];
    const float* Wo     = (const float*)d_in[5];
    const float* qw     = (const float*)d_in[6];
    const float* kw     = (const float*)d_in[7];
    float* out = (float*)d_out;

    float *gq, *gk, *gv, *gattn, *ggate;
    cudaGetSymbolAddress((void**)&gq,    g_q);
    cudaGetSymbolAddress((void**)&gk,    g_k);
    cudaGetSymbolAddress((void**)&gv,    g_v);
    cudaGetSymbolAddress((void**)&gattn, g_attn);
    cudaGetSymbolAddress((void**)&ggate, g_gate);

    cudaFuncSetAttribute(attn_kernel,
                         cudaFuncAttributeMaxDynamicSharedMemorySize, ATT_SMEM);

    dim3 gg(16, 16);
    gemm_f32<<<gg, 256>>>(hidden, Wq, gq, 2064);   // q part (cols 0..2047)
    gemm_f32<<<gg, 256>>>(hidden, Wk, gk, 2048);
    gemm_f32<<<gg, 256>>>(hidden, Wv, gv, 2048);
    gate_kernel<<<32, 256>>>(hidden, Wq, ggate);
    norm_rope<<<dim3(2048, 2), 256>>>(gq, gk, qw, kw, pos);
    attn_kernel<<<dim3(32, 16), 256, ATT_SMEM>>>(gq, gk, gv, ggate, gattn);
    gemm_f32<<<gg, 256>>>(gattn, Wo, out, 2048);
}

// round 6
// speedup vs baseline: 1.4795x; 1.4795x over previous
#include <cuda_runtime.h>
#include <cuda_bf16.h>
#include <math.h>
#include <stdint.h>

#define TT   2048
#define HID  2048
#define NH   16
#define DH   128

// ---------------- scratch (static device memory; no allocations) -------------
__device__ float g_q[TT * HID];
__device__ float g_k[TT * HID];
__device__ float g_v[TT * HID];
__device__ float g_gate[TT * NH];
__device__ __nv_bfloat16 g_hhi[TT * HID], g_hlo[TT * HID];
__device__ __nv_bfloat16 g_wqh[HID * HID], g_wql[HID * HID];
__device__ __nv_bfloat16 g_wkh[HID * HID], g_wkl[HID * HID];
__device__ __nv_bfloat16 g_wvh[HID * HID], g_wvl[HID * HID];
__device__ __nv_bfloat16 g_woh[HID * HID], g_wol[HID * HID];
__device__ __nv_bfloat16 g_ahi[TT * HID], g_alo[TT * HID];

// ---------------- portable PTX helpers (sm_80-era, compute_103-safe) ---------
__device__ __forceinline__ uint32_t smem_u32(const void* p) {
    uint32_t a;
    asm("{ .reg .u64 t; cvta.to.shared.u64 t, %1; cvt.u32.u64 %0, t; }" : "=r"(a) : "l"(p));
    return a;
}
__device__ __forceinline__ void cp16(uint32_t dst, const void* src) {
    asm volatile("cp.async.cg.shared.global [%0], [%1], 16;" :: "r"(dst), "l"(src) : "memory");
}
__device__ __forceinline__ void ldsm4(uint32_t* r, uint32_t addr) {
    asm volatile("ldmatrix.sync.aligned.m8n8.x4.shared.b16 {%0,%1,%2,%3}, [%4];"
                 : "=r"(r[0]), "=r"(r[1]), "=r"(r[2]), "=r"(r[3]) : "r"(addr));
}
__device__ __forceinline__ void mma16816(float* d, const uint32_t* a,
                                         uint32_t b0, uint32_t b1) {
    asm volatile(
        "mma.sync.aligned.m16n8k16.row.col.f32.bf16.bf16.f32 "
        "{%0,%1,%2,%3}, {%4,%5,%6,%7}, {%8,%9}, {%0,%1,%2,%3};"
        : "+f"(d[0]), "+f"(d[1]), "+f"(d[2]), "+f"(d[3])
        : "r"(a[0]), "r"(a[1]), "r"(a[2]), "r"(a[3]), "r"(b0), "r"(b1));
}

// ============================================================================
// split: f32 -> (hi, lo) bf16 pair. hi = bf16(x), lo = bf16(x - hi).
// ============================================================================
__global__ __launch_bounds__(256)
void split_kernel(const float* __restrict__ x, __nv_bfloat16* __restrict__ hi,
                  __nv_bfloat16* __restrict__ lo)
{
    int i = (blockIdx.x * 256 + threadIdx.x) * 4;
    float4 v = *(const float4*)(x + i);
    __nv_bfloat162 ph0 = __floats2bfloat162_rn(v.x, v.y);
    __nv_bfloat162 ph1 = __floats2bfloat162_rn(v.z, v.w);
    float2 f0 = __bfloat1622float2(ph0);
    float2 f1 = __bfloat1622float2(ph1);
    __nv_bfloat162 pl0 = __floats2bfloat162_rn(v.x - f0.x, v.y - f0.y);
    __nv_bfloat162 pl1 = __floats2bfloat162_rn(v.z - f1.x, v.w - f1.y);
    *(__nv_bfloat162*)(hi + i)     = ph0;
    *(__nv_bfloat162*)(hi + i + 2) = ph1;
    *(__nv_bfloat162*)(lo + i)     = pl0;
    *(__nv_bfloat162*)(lo + i + 2) = pl1;
}

// ============================================================================
// transpose + split: W[K=2048][ldw] -> Wt_hi/lo [N][K]
// ============================================================================
__global__ __launch_bounds__(256)
void transpose_split(const float* __restrict__ W, int ldw,
                     __nv_bfloat16* __restrict__ hi, __nv_bfloat16* __restrict__ lo)
{
    __shared__ float t[32][33];
    const int n0 = blockIdx.x * 32, k0 = blockIdx.y * 32;
    const int tx = threadIdx.x & 31, ty = threadIdx.x >> 5;
#pragma unroll
    for (int r = 0; r < 4; r++)
        t[ty + 8 * r][tx] = W[(size_t)(k0 + ty + 8 * r) * ldw + n0 + tx];
    __syncthreads();
#pragma unroll
    for (int r = 0; r < 4; r++) {
        int n = n0 + ty + 8 * r;
        float v = t[tx][ty + 8 * r];
        __nv_bfloat16 h = __float2bfloat16(v);
        hi[(size_t)n * HID + k0 + tx] = h;
        lo[(size_t)n * HID + k0 + tx] = __float2bfloat16(v - __bfloat162float(h));
    }
}

// ============================================================================
// mma.sync bf16x3 GEMM: C[2048x2048] = (Ahi+Alo) @ (Bhi+Blo)^T  (B is [N][K])
// CTA 128x128, BK=32, 8 warps (4m x 2n), 2-stage cp.async pipeline.
// smem per matrix: 128 rows x 40 bf16 (80B stride, conflict-free ldmatrix).
// ============================================================================
#define MAT_B   10240                 // 128*40*2 bytes per matrix
#define STAGE_B (4 * MAT_B)           // Ah, Al, Bh, Bl
#define GEMM_SMEM (2 * STAGE_B)       // 81920

__global__ __launch_bounds__(256, 2)
void gemm_bf16x3(const __nv_bfloat16* __restrict__ Ah, const __nv_bfloat16* __restrict__ Al,
                 const __nv_bfloat16* __restrict__ Bh, const __nv_bfloat16* __restrict__ Bl,
                 float* __restrict__ C)
{
    extern __shared__ char sm[];
    const uint32_t sb = smem_u32(sm);

    const int tid  = threadIdx.x;
    const int lane = tid & 31;
    const int wid  = tid >> 5;
    const int wm   = wid & 3;          // 4 warps over M (32 rows each)
    const int wn   = wid >> 2;         // 2 warps over N (64 cols each)
    const int bm = blockIdx.y * 128, bn = blockIdx.x * 128;

    const __nv_bfloat16* gsrc[4] = {
        Ah + (size_t)bm * HID, Al + (size_t)bm * HID,
        Bh + (size_t)bn * HID, Bl + (size_t)bn * HID };

    // cp.async: per matrix 128 rows x 4 x 16B segments = 512; 2 per thread
    const int ld_row = tid >> 2;            // 0..63  (rep adds 64)
    const int ld_seg = (tid & 3) * 16;      // byte offset in row

    // ldmatrix per-lane addressing
    const int a_row  = wm * 32 + (lane & 15);
    const int a_koff = (lane >> 4) * 8;                         // elements
    const int b_nrow = wn * 64 + (lane & 7) + ((lane >> 4) & 1) * 8;
    const int b_koff = ((lane >> 3) & 1) * 8;

    float acc[2][8][4];
#pragma unroll
    for (int mt = 0; mt < 2; mt++)
#pragma unroll
        for (int nt = 0; nt < 8; nt++)
#pragma unroll
            for (int i = 0; i < 4; i++) acc[mt][nt][i] = 0.f;

    // ---- prologue: stage 0 ----
    {
        const uint32_t st = sb;
#pragma unroll
        for (int m = 0; m < 4; m++)
#pragma unroll
            for (int rep = 0; rep < 2; rep++) {
                int row = ld_row + rep * 64;
                cp16(st + m * MAT_B + row * 80 + ld_seg,
                     (const char*)(gsrc[m] + (size_t)row * HID) + ld_seg);
            }
        asm volatile("cp.async.commit_group;" ::: "memory");
    }

    for (int c = 0; c < 64; c++) {
        if (c + 1 < 64) {
            const uint32_t st = sb + ((c + 1) & 1) * STAGE_B;
            const int kb = (c + 1) * 64;     // byte offset along K (32 elems)
#pragma unroll
            for (int m = 0; m < 4; m++)
#pragma unroll
                for (int rep = 0; rep < 2; rep++) {
                    int row = ld_row + rep * 64;
                    cp16(st + m * MAT_B + row * 80 + ld_seg,
                         (const char*)(gsrc[m] + (size_t)row * HID) + kb + ld_seg);
                }
            asm volatile("cp.async.commit_group;" ::: "memory");
            asm volatile("cp.async.wait_group 1;" ::: "memory");
        } else {
            asm volatile("cp.async.wait_group 0;" ::: "memory");
        }
        __syncthreads();

        const uint32_t st = sb + (c & 1) * STAGE_B;
#pragma unroll
        for (int ks = 0; ks < 2; ks++) {
            uint32_t ah[2][4], al[2][4];
#pragma unroll
            for (int mt = 0; mt < 2; mt++) {
                uint32_t ar = st + ((a_row + mt * 16) * 40 + ks * 16 + a_koff) * 2;
                ldsm4(ah[mt], ar);
                ldsm4(al[mt], ar + MAT_B);
            }
#pragma unroll
            for (int np = 0; np < 4; np++) {
                uint32_t br = st + 2 * MAT_B +
                              ((b_nrow + np * 16) * 40 + ks * 16 + b_koff) * 2;
                uint32_t bh[4], bl[4];
                ldsm4(bh, br);
                ldsm4(bl, br + MAT_B);
#pragma unroll
                for (int mt = 0; mt < 2; mt++) {
                    mma16816(acc[mt][np * 2],     ah[mt], bh[0], bh[1]);
                    mma16816(acc[mt][np * 2],     ah[mt], bl[0], bl[1]);
                    mma16816(acc[mt][np * 2],     al[mt], bh[0], bh[1]);
                    mma16816(acc[mt][np * 2 + 1], ah[mt], bh[2], bh[3]);
                    mma16816(acc[mt][np * 2 + 1], ah[mt], bl[2], bl[3]);
                    mma16816(acc[mt][np * 2 + 1], al[mt], bh[2], bh[3]);
                }
            }
        }
        __syncthreads();
    }

    // ---- epilogue ----
#pragma unroll
    for (int mt = 0; mt < 2; mt++) {
        const int r0 = bm + wm * 32 + mt * 16 + (lane >> 2);
#pragma unroll
        for (int nt = 0; nt < 8; nt++) {
            const int col = bn + wn * 64 + nt * 8 + (lane & 3) * 2;
            *(float2*)(C + (size_t)r0 * HID + col) =
                make_float2(acc[mt][nt][0], acc[mt][nt][1]);
            *(float2*)(C + (size_t)(r0 + 8) * HID + col) =
                make_float2(acc[mt][nt][2], acc[mt][nt][3]);
        }
    }
}

// ============================================================================
// gate logits: gate[T][16] = hidden @ Wq[:, 2048:2064]  (fp32, exact sign)
// ============================================================================
__global__ __launch_bounds__(256)
void gate_kernel(const float* __restrict__ A, const float* __restrict__ Wq,
                 float* __restrict__ gate)
{
    __shared__ float As[16][132];
    __shared__ float Ws[128][17];
    const int t0  = blockIdx.x * 16;
    const int tid = threadIdx.x;
    const int tok = tid >> 4, gg = tid & 15;
    float acc = 0.f;

    for (int k0 = 0; k0 < 2048; k0 += 128) {
#pragma unroll
        for (int i = 0; i < 2; i++) {
            int idx = tid + 256 * i;
            int r = idx >> 5, c = (idx & 31) * 4;
            *(float4*)&As[r][c] = *(const float4*)(A + (size_t)(t0 + r) * 2048 + k0 + c);
        }
#pragma unroll
        for (int i = 0; i < 8; i++) {
            int j = tid + 256 * i;
            int r = j >> 4, cg = j & 15;
            Ws[r][cg] = Wq[(size_t)(k0 + r) * 2064 + 2048 + cg];
        }
        __syncthreads();
#pragma unroll 8
        for (int k = 0; k < 128; k++)
            acc += As[tok][k] * Ws[k][gg];
        __syncthreads();
    }
    gate[(size_t)(t0 + tok) * 16 + gg] = acc;
}

// ============================================================================
// RMSNorm (over full 2048) + RoPE (per head, D=128), in place.
// ============================================================================
__global__ __launch_bounds__(256)
void norm_rope(float* __restrict__ xq, float* __restrict__ xk,
               const float* __restrict__ qw, const float* __restrict__ kw,
               const int* __restrict__ pos)
{
    const int t = blockIdx.x;
    float* row      = (blockIdx.y == 0 ? xq : xk) + (size_t)t * 2048;
    const float* w  = (blockIdx.y == 0 ? qw : kw);

    __shared__ float sm[2048];
    __shared__ float red[8];

    float ss = 0.f;
    for (int i = threadIdx.x; i < 2048; i += 256) {
        float v = row[i]; sm[i] = v; ss += v * v;
    }
#pragma unroll
    for (int o = 16; o; o >>= 1) ss += __shfl_xor_sync(0xffffffffu, ss, o);
    if ((threadIdx.x & 31) == 0) red[threadIdx.x >> 5] = ss;
    __syncthreads();

    float tot = 0.f;
#pragma unroll
    for (int i = 0; i < 8; i++) tot += red[i];
    const float rinv = rsqrtf(tot * (1.0f / 2048.0f) + 1e-6f);
    const float p = (float)pos[t];

    for (int pr = threadIdx.x; pr < 1024; pr += 256) {
        int hh = pr >> 6, i = pr & 63;
        float invf = powf(500000.0f, -(float)(2 * i) * (1.0f / 128.0f));
        float ang = p * invf;
        float sn, cs; sincosf(ang, &sn, &cs);
        int i1 = hh * 128 + i, i2 = i1 + 64;
        float x1 = sm[i1] * rinv * w[i1];
        float x2 = sm[i2] * rinv * w[i2];
        row[i1] = x1 * cs - x2 * sn;
        row[i2] = x2 * cs + x1 * sn;
    }
}

// ============================================================================
// Fused gated attention (flash-2, fp32). Epilogue writes hi/lo bf16 split.
// ============================================================================
#define ATT_SMEM ((128*64*2 + 64*128 + 64*68 + 4*64) * 4)

__device__ __forceinline__ void fma8(float* o, float p, float4 va, float4 vb)
{
    o[0] += p * va.x; o[1] += p * va.y; o[2] += p * va.z; o[3] += p * va.w;
    o[4] += p * vb.x; o[5] += p * vb.y; o[6] += p * vb.z; o[7] += p * vb.w;
}

__global__ __launch_bounds__(256)
void attn_kernel(const float* __restrict__ gq, const float* __restrict__ gk,
                 const float* __restrict__ gv, const float* __restrict__ gate,
                 __nv_bfloat16* __restrict__ ahi, __nv_bfloat16* __restrict__ alo)
{
    extern __shared__ float smx[];
    float* Qs = smx;                 // [128][64]  d-major
    float* Ks = Qs + 128 * 64;       // [128][64]  d-major
    float* Vs = Ks + 128 * 64;       // [64][128]  k-major
    float* Ss = Vs + 64 * 128;       // [64][68]
    float* aS = Ss + 64 * 68;
    float* mS = aS + 64;
    float* lS = mS + 64;
    float* gS = lS + 64;

    const int tid = threadIdx.x;
    const int qt = blockIdx.x, h = blockIdx.y;
    const int t0 = qt * 64;
    const float scale = 0.08838834764831843f;

    for (int idx = tid; idx < 64 * 128; idx += 256) {
        int r = idx >> 7, d = idx & 127;
        Qs[d * 64 + r] = gq[(size_t)(t0 + r) * 2048 + h * 128 + d];
    }
    if (tid < 64) {
        mS[tid] = -1e30f; lS[tid] = 0.f;
        gS[tid] = (gate[(size_t)(t0 + tid) * 16 + h] > 0.f) ? 1.f : 0.f;
    }

    const int tq   = tid & 15, tk  = tid >> 4;
    const int td   = tid & 15, tq2 = tid >> 4;
    const int srow = tid >> 2, spart = tid & 3;

    float O[4][8];
#pragma unroll
    for (int i = 0; i < 4; i++)
#pragma unroll
        for (int j = 0; j < 8; j++) O[i][j] = 0.f;

    for (int kt = 0; kt <= qt; kt++) {
        const int k0 = kt * 64;
        __syncthreads();
        for (int idx = tid; idx < 64 * 128; idx += 256) {
            int r = idx >> 7, d = idx & 127;
            Ks[d * 64 + r] = gk[(size_t)(k0 + r) * 2048 + h * 128 + d];
            Vs[idx]        = gv[(size_t)(k0 + r) * 2048 + h * 128 + d];
        }
        __syncthreads();

        float s[4][4];
#pragma unroll
        for (int i = 0; i < 4; i++)
#pragma unroll
            for (int j = 0; j < 4; j++) s[i][j] = 0.f;

        const float* Qb = Qs + tq * 4;
        const float* Kb = Ks + tk * 4;
#pragma unroll 4
        for (int d = 0; d < 128; d++) {
            const float4 a = *(const float4*)(Qb + d * 64);
            const float4 b = *(const float4*)(Kb + d * 64);
            s[0][0] += a.x*b.x; s[0][1] += a.x*b.y; s[0][2] += a.x*b.z; s[0][3] += a.x*b.w;
            s[1][0] += a.y*b.x; s[1][1] += a.y*b.y; s[1][2] += a.y*b.z; s[1][3] += a.y*b.w;
            s[2][0] += a.z*b.x; s[2][1] += a.z*b.y; s[2][2] += a.z*b.z; s[2][3] += a.z*b.w;
            s[3][0] += a.w*b.x; s[3][1] += a.w*b.y; s[3][2] += a.w*b.z; s[3][3] += a.w*b.w;
        }

        const int jb = k0 + tk * 4;
#pragma unroll
        for (int i = 0; i < 4; i++) {
            const int q  = tq * 4 + i;
            const int tg = t0 + q;
            const bool glob = gS[q] > 0.5f;
            const int lo = glob ? -0x7fffffff : (tg - 127);
            float4 o;
            o.x = (jb + 0 <= tg && jb + 0 >= lo) ? s[i][0] * scale : -1e30f;
            o.y = (jb + 1 <= tg && jb + 1 >= lo) ? s[i][1] * scale : -1e30f;
            o.z = (jb + 2 <= tg && jb + 2 >= lo) ? s[i][2] * scale : -1e30f;
            o.w = (jb + 3 <= tg && jb + 3 >= lo) ? s[i][3] * scale : -1e30f;
            *(float4*)(Ss + q * 68 + tk * 4) = o;
        }
        __syncthreads();

        {
            float* rowp = Ss + srow * 68 + spart * 16;
            float mloc = -1e30f;
#pragma unroll
            for (int c = 0; c < 16; c++) mloc = fmaxf(mloc, rowp[c]);
            mloc = fmaxf(mloc, __shfl_xor_sync(0xffffffffu, mloc, 1));
            mloc = fmaxf(mloc, __shfl_xor_sync(0xffffffffu, mloc, 2));
            const float mold = mS[srow];
            const float mnew = fmaxf(mold, mloc);
            float lsum = 0.f;
#pragma unroll
            for (int c = 0; c < 16; c++) {
                float v = rowp[c];
                float pp = (v > -1e29f) ? expf(v - mnew) : 0.f;
                rowp[c] = pp; lsum += pp;
            }
            lsum += __shfl_xor_sync(0xffffffffu, lsum, 1);
            lsum += __shfl_xor_sync(0xffffffffu, lsum, 2);
            if (spart == 0) {
                float alpha = expf(mold - mnew);
                lS[srow] = lS[srow] * alpha + lsum;
                mS[srow] = mnew;
                aS[srow] = alpha;
            }
        }
        __syncthreads();

        {
            const int q0 = tq2 * 4, d0 = td * 8;
            const float al0 = aS[q0], al1 = aS[q0+1], al2 = aS[q0+2], al3 = aS[q0+3];
#pragma unroll
            for (int j = 0; j < 8; j++) {
                O[0][j] *= al0; O[1][j] *= al1; O[2][j] *= al2; O[3][j] *= al3;
            }
            for (int kk = 0; kk < 64; kk += 4) {
                float4 p0 = *(const float4*)(Ss + (q0+0) * 68 + kk);
                float4 p1 = *(const float4*)(Ss + (q0+1) * 68 + kk);
                float4 p2 = *(const float4*)(Ss + (q0+2) * 68 + kk);
                float4 p3 = *(const float4*)(Ss + (q0+3) * 68 + kk);
                const float* vb = Vs + kk * 128 + d0;
                float4 va0, va1;
                va0 = *(const float4*)(vb);            va1 = *(const float4*)(vb + 4);
                fma8(O[0], p0.x, va0, va1); fma8(O[1], p1.x, va0, va1);
                fma8(O[2], p2.x, va0, va1); fma8(O[3], p3.x, va0, va1);
                va0 = *(const float4*)(vb + 128);      va1 = *(const float4*)(vb + 132);
                fma8(O[0], p0.y, va0, va1); fma8(O[1], p1.y, va0, va1);
                fma8(O[2], p2.y, va0, va1); fma8(O[3], p3.y, va0, va1);
                va0 = *(const float4*)(vb + 256);      va1 = *(const float4*)(vb + 260);
                fma8(O[0], p0.z, va0, va1); fma8(O[1], p1.z, va0, va1);
                fma8(O[2], p2.z, va0, va1); fma8(O[3], p3.z, va0, va1);
                va0 = *(const float4*)(vb + 384);      va1 = *(const float4*)(vb + 388);
                fma8(O[0], p0.w, va0, va1); fma8(O[1], p1.w, va0, va1);
                fma8(O[2], p2.w, va0, va1); fma8(O[3], p3.w, va0, va1);
            }
        }
    }

    // ---- epilogue: normalize, split to bf16 hi/lo ----
    {
        const int q0 = tq2 * 4, d0 = td * 8;
#pragma unroll
        for (int i = 0; i < 4; i++) {
            const float linv = 1.0f / lS[q0 + i];
            const int t = t0 + q0 + i;
            __align__(16) __nv_bfloat16 hb[8], lb[8];
#pragma unroll
            for (int j = 0; j < 8; j++) {
                float v = O[i][j] * linv;
                __nv_bfloat16 hh = __float2bfloat16(v);
                hb[j] = hh;
                lb[j] = __float2bfloat16(v - __bfloat162float(hh));
            }
            *(uint4*)(ahi + (size_t)t * 2048 + h * 128 + d0) = *(uint4*)hb;
            *(uint4*)(alo + (size_t)t * 2048 + h * 128 + d0) = *(uint4*)lb;
        }
    }
}

// ============================================================================
extern "C" void kernel_launch(void* const* d_in, const int* in_sizes, int n_in,
                              void* d_out, int out_size)
{
    const float* hidden = (const float*)d_in[0];
    const int*   pos    = (const int*)  d_in[1];
    const float* Wq     = (const float*)d_in[2];
    const float* Wk     = (const float*)d_in[3];
    const float* Wv     = (const float*)d_in[4];
    const float* Wo     = (const float*)d_in[5];
    const float* qw     = (const float*)d_in[6];
    const float* kw     = (const float*)d_in[7];
    float* out = (float*)d_out;

    float *gq, *gk, *gv, *ggate;
    __nv_bfloat16 *hhi, *hlo, *wqh, *wql, *wkh, *wkl, *wvh, *wvl, *woh, *wol, *ahi, *alo;
    cudaGetSymbolAddress((void**)&gq,   g_q);
    cudaGetSymbolAddress((void**)&gk,   g_k);
    cudaGetSymbolAddress((void**)&gv,   g_v);
    cudaGetSymbolAddress((void**)&ggate,g_gate);
    cudaGetSymbolAddress((void**)&hhi,  g_hhi);  cudaGetSymbolAddress((void**)&hlo, g_hlo);
    cudaGetSymbolAddress((void**)&wqh,  g_wqh);  cudaGetSymbolAddress((void**)&wql, g_wql);
    cudaGetSymbolAddress((void**)&wkh,  g_wkh);  cudaGetSymbolAddress((void**)&wkl, g_wkl);
    cudaGetSymbolAddress((void**)&wvh,  g_wvh);  cudaGetSymbolAddress((void**)&wvl, g_wvl);
    cudaGetSymbolAddress((void**)&woh,  g_woh);  cudaGetSymbolAddress((void**)&wol, g_wol);
    cudaGetSymbolAddress((void**)&ahi,  g_ahi);  cudaGetSymbolAddress((void**)&alo, g_alo);

    cudaFuncSetAttribute(attn_kernel,
                         cudaFuncAttributeMaxDynamicSharedMemorySize, ATT_SMEM);
    cudaFuncSetAttribute(gemm_bf16x3,
                         cudaFuncAttributeMaxDynamicSharedMemorySize, GEMM_SMEM);

    dim3 gg(16, 16);

    split_kernel<<<TT * HID / 1024, 256>>>(hidden, hhi, hlo);
    transpose_split<<<dim3(64, 64), 256>>>(Wq, 2064, wqh, wql);
    transpose_split<<<dim3(64, 64), 256>>>(Wk, 2048, wkh, wkl);
    transpose_split<<<dim3(64, 64), 256>>>(Wv, 2048, wvh, wvl);
    transpose_split<<<dim3(64, 64), 256>>>(Wo, 2048, woh, wol);
    gate_kernel<<<128, 256>>>(hidden, Wq, ggate);

    gemm_bf16x3<<<gg, 256, GEMM_SMEM>>>(hhi, hlo, wqh, wql, gq);
    gemm_bf16x3<<<gg, 256, GEMM_SMEM>>>(hhi, hlo, wkh, wkl, gk);
    gemm_bf16x3<<<gg, 256, GEMM_SMEM>>>(hhi, hlo, wvh, wvl, gv);

    norm_rope<<<dim3(2048, 2), 256>>>(gq, gk, qw, kw, pos);
    attn_kernel<<<dim3(32, 16), 256, ATT_SMEM>>>(gq, gk, gv, ggate, ahi, alo);

    gemm_bf16x3<<<gg, 256, GEMM_SMEM>>>(ahi, alo, woh, wol, out);
}